// round 1
// baseline (speedup 1.0000x reference)
#include <cuda_runtime.h>
#include <cstdint>

// Problem dims
#define BB 4
#define MM 112        // slices
#define CCH 512       // channels
#define HWP 256       // 16*16 spatial
#define CC2 1024      // 2*C
#define LOUT 49       // conv1d output length
#define NOC 64        // conv1d out channels
#define NSPLIT 128    // split-K CTAs (each owns 8 ic of 1024)
#define WS_LD 68      // padded smem row for W (conflict-free: 68 mod 32 = 4)

// Device scratch (static globals — no runtime allocation)
__device__ float g_x[BB * CC2 * MM];              // [b][c][m] : c<512 = fv mean, c>=512 = fv max
__device__ float g_feato[BB * CC2];               // [b][0..512)=feat_o_avg, [512..1024)=feat_o_max
__device__ float g_part[NSPLIT][BB * 64 * NOC];   // split-K partials [split][(b*64+l)*64+oc]
__device__ float g_sw[BB * NOC * LOUT];           // slice_weights [b][oc][l]

// ---------------------------------------------------------------------------
// Kernel 1: global avg + max pool over 16x16 maps. One warp per (b,m,c) slab.
// Reads 235 MB coalesced (float4), writes fv/fv_max in [b][c][m] GEMM layout.
// ---------------------------------------------------------------------------
__global__ void pool_kernel(const float* __restrict__ oct) {
    int warp = (blockIdx.x * blockDim.x + threadIdx.x) >> 5;  // 0..229375
    int lane = threadIdx.x & 31;
    const float4* p = reinterpret_cast<const float4*>(oct) + (size_t)warp * 64;
    float4 v0 = p[lane];
    float4 v1 = p[lane + 32];
    float s  = (v0.x + v0.y) + (v0.z + v0.w) + (v1.x + v1.y) + (v1.z + v1.w);
    float mx = fmaxf(fmaxf(fmaxf(v0.x, v0.y), fmaxf(v0.z, v0.w)),
                     fmaxf(fmaxf(v1.x, v1.y), fmaxf(v1.z, v1.w)));
#pragma unroll
    for (int o = 16; o; o >>= 1) {
        s  += __shfl_xor_sync(0xffffffffu, s, o);
        mx  = fmaxf(mx, __shfl_xor_sync(0xffffffffu, mx, o));
    }
    if (lane == 0) {
        int c = warp & 511;
        int m = (warp >> 9) % MM;
        int b = warp / (MM * CCH);
        g_x[((b * CC2) + c) * MM + m]       = s * (1.0f / 256.0f);
        g_x[((b * CC2) + 512 + c) * MM + m] = mx;
    }
}

// ---------------------------------------------------------------------------
// Kernel 2: feat_o. feat_o_avg[b,c] = max_m fv; feat_o_max[b,c] = fv[argmax fv_max].
// One warp per (b,c). First-index tie rule to match jnp.argmax.
// ---------------------------------------------------------------------------
__global__ void argsel_kernel() {
    int warp = (blockIdx.x * blockDim.x + threadIdx.x) >> 5;  // 0..2047
    int lane = threadIdx.x & 31;
    int b = warp >> 9, c = warp & 511;
    const float* fv = g_x + (b * CC2 + c) * MM;
    const float* fm = g_x + (b * CC2 + 512 + c) * MM;
    float maxfv = -1e30f;
    float maxfm = -1e30f;
    int idx = 0x7fffffff;
    for (int m = lane; m < MM; m += 32) {
        float a = fv[m];
        maxfv = fmaxf(maxfv, a);
        float q = fm[m];
        if (q > maxfm) { maxfm = q; idx = m; }
    }
#pragma unroll
    for (int o = 16; o; o >>= 1) {
        maxfv = fmaxf(maxfv, __shfl_xor_sync(0xffffffffu, maxfv, o));
        float ov = __shfl_xor_sync(0xffffffffu, maxfm, o);
        int   oi = __shfl_xor_sync(0xffffffffu, idx,   o);
        if (ov > maxfm || (ov == maxfm && oi < idx)) { maxfm = ov; idx = oi; }
    }
    if (lane == 0) {
        g_feato[b * CC2 + c]       = maxfv;
        g_feato[b * CC2 + 512 + c] = fv[idx];
    }
}

// ---------------------------------------------------------------------------
// Kernel 3: conv1d as split-K tf32 tensor-core GEMM.
//   out[b,l,oc] = sum_{ic,k} x[b,ic,l+k] * w[oc,ic,k],  K = 1024*64 = 65536.
// Grid = 128 CTAs, each owns 8 ic (K-chunk 512), computes the full M=256
// (4 batches x 64 padded rows) x N=64 tile, writes a partial.
// ---------------------------------------------------------------------------
__device__ __forceinline__ float to_tf32(float x) {
    uint32_t u;
    asm("cvt.rna.tf32.f32 %0, %1;" : "=r"(u) : "f"(x));
    return __uint_as_float(u);
}

extern "C" __global__ void __launch_bounds__(256, 1)
gemm_kernel(const float* __restrict__ w) {
    extern __shared__ float sh[];
    float* xs = sh;            // [4][8][128] = 4096 floats (x rows, zero-padded past m=111)
    float* ws = sh + 4096;     // [2][64][WS_LD] double-buffered W chunk

    const int tid = threadIdx.x;
    const int split = blockIdx.x;
    const int ic0 = split * 8;

    // Stage x rows for all 4 batches, 8 ic each (converted to tf32 once).
    for (int i = tid; i < 4096; i += 256) {
        int m = i & 127, j = (i >> 7) & 7, b = i >> 10;
        float v = (m < MM) ? g_x[(b * CC2 + ic0 + j) * MM + m] : 0.0f;
        xs[i] = to_tf32(v);
    }
    // Stage W for j=0.
    for (int i = tid; i < 4096; i += 256) {
        int k = i & 63, oc = i >> 6;
        ws[oc * WS_LD + k] = to_tf32(w[(size_t)oc * 65536 + (size_t)ic0 * 64 + k]);
    }
    __syncthreads();

    const int wid = tid >> 5, lane = tid & 31;
    const int b = wid >> 1, mhalf = wid & 1;       // warp -> (batch, m-half)
    const int g = lane >> 2, t = lane & 3;
    const float* xb = xs + b * 8 * 128;

    float acc[2][8][4];
#pragma unroll
    for (int a = 0; a < 2; a++)
#pragma unroll
        for (int n = 0; n < 8; n++)
#pragma unroll
            for (int q = 0; q < 4; q++) acc[a][n][q] = 0.0f;

    float nxt[16];
    for (int j = 0; j < 8; j++) {
        const float* wb = ws + (j & 1) * 64 * WS_LD;
        if (j < 7) {
#pragma unroll
            for (int i = 0; i < 16; i++) {
                int ii = tid + i * 256;
                int k = ii & 63, oc = ii >> 6;
                nxt[i] = w[(size_t)oc * 65536 + (size_t)(ic0 + j + 1) * 64 + k];
            }
        }
        const float* xr = xb + j * 128;
#pragma unroll
        for (int k0 = 0; k0 < 64; k0 += 8) {
            uint32_t a0[2], a1[2], a2[2], a3[2];
#pragma unroll
            for (int mt = 0; mt < 2; mt++) {
                int lb = mhalf * 32 + mt * 16 + g;
                a0[mt] = __float_as_uint(xr[lb     + k0 + t]);
                a1[mt] = __float_as_uint(xr[lb + 8 + k0 + t]);
                a2[mt] = __float_as_uint(xr[lb     + k0 + t + 4]);
                a3[mt] = __float_as_uint(xr[lb + 8 + k0 + t + 4]);
            }
#pragma unroll
            for (int nt = 0; nt < 8; nt++) {
                uint32_t b0 = __float_as_uint(wb[(nt * 8 + g) * WS_LD + k0 + t]);
                uint32_t b1 = __float_as_uint(wb[(nt * 8 + g) * WS_LD + k0 + t + 4]);
#pragma unroll
                for (int mt = 0; mt < 2; mt++) {
                    asm volatile(
                        "mma.sync.aligned.m16n8k8.row.col.f32.tf32.tf32.f32 "
                        "{%0,%1,%2,%3}, {%4,%5,%6,%7}, {%8,%9}, {%0,%1,%2,%3};"
                        : "+f"(acc[mt][nt][0]), "+f"(acc[mt][nt][1]),
                          "+f"(acc[mt][nt][2]), "+f"(acc[mt][nt][3])
                        : "r"(a0[mt]), "r"(a1[mt]), "r"(a2[mt]), "r"(a3[mt]),
                          "r"(b0), "r"(b1));
                }
            }
        }
        if (j < 7) {
            float* wd = ws + ((j + 1) & 1) * 64 * WS_LD;
#pragma unroll
            for (int i = 0; i < 16; i++) {
                int ii = tid + i * 256;
                int k = ii & 63, oc = ii >> 6;
                wd[oc * WS_LD + k] = to_tf32(nxt[i]);
            }
        }
        __syncthreads();
    }

    // Write partial tile.
    float* po = &g_part[split][0];
#pragma unroll
    for (int mt = 0; mt < 2; mt++) {
        int row0 = mhalf * 32 + mt * 16 + g;
#pragma unroll
        for (int nt = 0; nt < 8; nt++) {
            int col = nt * 8 + 2 * t;
            float2 v01 = make_float2(acc[mt][nt][0], acc[mt][nt][1]);
            float2 v23 = make_float2(acc[mt][nt][2], acc[mt][nt][3]);
            *reinterpret_cast<float2*>(po + (size_t)(b * 64 + row0)     * 64 + col) = v01;
            *reinterpret_cast<float2*>(po + (size_t)(b * 64 + row0 + 8) * 64 + col) = v23;
        }
    }
}

// ---------------------------------------------------------------------------
// Kernel 4: reduce split-K partials + bias + sigmoid -> slice_weights.
// ---------------------------------------------------------------------------
__global__ void reduce_kernel(const float* __restrict__ bias) {
    int idx = blockIdx.x * 256 + threadIdx.x;  // 0..16383
    float s = 0.0f;
#pragma unroll 8
    for (int sp = 0; sp < NSPLIT; sp++) s += g_part[sp][idx];
    int oc = idx & 63, l = (idx >> 6) & 63, b = idx >> 12;
    if (l < LOUT) {
        float z = s + bias[oc];
        g_sw[(b * NOC + oc) * LOUT + l] = 1.0f / (1.0f + __expf(-z));
    }
}

// ---------------------------------------------------------------------------
// Kernel 5: convf -> r[13][13], attended mean -> feat_f, head -> out[4,3].
// One block per batch.
// ---------------------------------------------------------------------------
__global__ void final_kernel(const float* __restrict__ featf,
                             const float* __restrict__ wf,
                             const float* __restrict__ bf,
                             const float* __restrict__ hw,
                             const float* __restrict__ hb,
                             float* __restrict__ out) {
    __shared__ float sw[NOC * LOUT];     // 3136
    __shared__ float wfs[13 * 64 * 5];   // 4160
    __shared__ float rs[169];
    __shared__ float feat[512];

    int b = blockIdx.x, tid = threadIdx.x;
    for (int i = tid; i < NOC * LOUT; i += 256) sw[i] = g_sw[b * NOC * LOUT + i];
    for (int i = tid; i < 13 * 64 * 5; i += 256) wfs[i] = wf[i];
    __syncthreads();

    if (tid < 169) {
        int j = tid / 13, i = tid % 13;
        float a = bf[j];
        for (int ci = 0; ci < 64; ci++) {
#pragma unroll
            for (int tt = 0; tt < 5; tt++) {
                int p = 4 * i - 2 + tt;
                if (p >= 0 && p < LOUT) a += wfs[(j * 64 + ci) * 5 + tt] * sw[ci * LOUT + p];
            }
        }
        rs[tid] = 1.0f / (1.0f + __expf(-a));
    }
    __syncthreads();

    int wid = tid >> 5, lane = tid & 31;
    for (int c = wid; c < 512; c += 8) {
        const float* fp = featf + (size_t)(b * 512 + c) * 169;
        float s = 0.0f;
        for (int p = lane; p < 169; p += 32) s += fp[p] * (1.0f + rs[p]);
#pragma unroll
        for (int o = 16; o; o >>= 1) s += __shfl_xor_sync(0xffffffffu, s, o);
        if (lane == 0) feat[c] = s * (1.0f / 169.0f);
    }
    __syncthreads();

    if (wid < 3) {
        float s = 0.0f;
        for (int c = lane; c < 1536; c += 32) {
            float f = (c < 512) ? feat[c] : g_feato[b * CC2 + (c - 512)];
            s += f * hw[wid * 1536 + c];
        }
#pragma unroll
        for (int o = 16; o; o >>= 1) s += __shfl_xor_sync(0xffffffffu, s, o);
        if (lane == 0) out[b * 3 + wid] = s + hb[wid];
    }
}

// ---------------------------------------------------------------------------
extern "C" void kernel_launch(void* const* d_in, const int* in_sizes, int n_in,
                              void* d_out, int out_size) {
    const float* featf = (const float*)d_in[0];   // [4,512,13,13]
    const float* oct   = (const float*)d_in[1];   // [4,112,512,16,16]
    const float* w1    = (const float*)d_in[2];   // [64,1024,64]
    const float* b1    = (const float*)d_in[3];   // [64]
    const float* wf    = (const float*)d_in[4];   // [13,64,5]
    const float* bf    = (const float*)d_in[5];   // [13]
    const float* hw    = (const float*)d_in[6];   // [3,1536]
    const float* hb    = (const float*)d_in[7];   // [3]
    float* out = (float*)d_out;                   // [4,3]

    pool_kernel<<<28672, 256>>>(oct);
    argsel_kernel<<<256, 256>>>();

    const int smem_bytes = (4096 + 2 * 64 * WS_LD) * sizeof(float);  // 51200
    cudaFuncSetAttribute(gemm_kernel, cudaFuncAttributeMaxDynamicSharedMemorySize,
                         smem_bytes);
    gemm_kernel<<<NSPLIT, 256, smem_bytes>>>(w1);

    reduce_kernel<<<64, 256>>>(b1);
    final_kernel<<<4, 256>>>(featf, wf, bf, hw, hb, out);
}

// round 2
// speedup vs baseline: 2.1665x; 2.1665x over previous
#include <cuda_runtime.h>
#include <cstdint>

#define BB 4
#define MM 112
#define CCH 512
#define CC2 1024
#define LOUT 49
#define NOC 64
#define NSPLIT 128
#define WS_LD 68   // padded smem row (68 mod 32 = 4 -> conflict-free B frags)

__device__ float g_x[BB * CC2 * MM];
__device__ float g_feato[BB * CC2];
__device__ float g_part[NSPLIT][BB * 64 * NOC];
__device__ float g_sw[BB * NOC * LOUT];
__device__ float g_rs[BB * 169];
__device__ float g_feat[BB * 512];

// ---------------------------------------------------------------------------
// Kernel 1: global avg + max pool. One warp per (b,m,c) 1KB slab.
// ---------------------------------------------------------------------------
__global__ void pool_kernel(const float* __restrict__ oct) {
    int warp = (blockIdx.x * blockDim.x + threadIdx.x) >> 5;
    int lane = threadIdx.x & 31;
    const float4* p = reinterpret_cast<const float4*>(oct) + (size_t)warp * 64;
    float4 v0 = p[lane];
    float4 v1 = p[lane + 32];
    float s  = (v0.x + v0.y) + (v0.z + v0.w) + (v1.x + v1.y) + (v1.z + v1.w);
    float mx = fmaxf(fmaxf(fmaxf(v0.x, v0.y), fmaxf(v0.z, v0.w)),
                     fmaxf(fmaxf(v1.x, v1.y), fmaxf(v1.z, v1.w)));
#pragma unroll
    for (int o = 16; o; o >>= 1) {
        s  += __shfl_xor_sync(0xffffffffu, s, o);
        mx  = fmaxf(mx, __shfl_xor_sync(0xffffffffu, mx, o));
    }
    if (lane == 0) {
        int c = warp & 511;
        int m = (warp >> 9) % MM;
        int b = warp / (MM * CCH);
        g_x[((b * CC2) + c) * MM + m]       = s * (1.0f / 256.0f);
        g_x[((b * CC2) + 512 + c) * MM + m] = mx;
    }
}

// ---------------------------------------------------------------------------
// Kernel 2: feat_o via argmax identities. One warp per (b,c).
// ---------------------------------------------------------------------------
__global__ void argsel_kernel() {
    int warp = (blockIdx.x * blockDim.x + threadIdx.x) >> 5;
    int lane = threadIdx.x & 31;
    int b = warp >> 9, c = warp & 511;
    const float* fv = g_x + (b * CC2 + c) * MM;
    const float* fm = g_x + (b * CC2 + 512 + c) * MM;
    float maxfv = -1e30f, maxfm = -1e30f;
    int idx = 0x7fffffff;
    for (int m = lane; m < MM; m += 32) {
        float a = fv[m];
        maxfv = fmaxf(maxfv, a);
        float q = fm[m];
        if (q > maxfm) { maxfm = q; idx = m; }
    }
#pragma unroll
    for (int o = 16; o; o >>= 1) {
        maxfv = fmaxf(maxfv, __shfl_xor_sync(0xffffffffu, maxfv, o));
        float ov = __shfl_xor_sync(0xffffffffu, maxfm, o);
        int   oi = __shfl_xor_sync(0xffffffffu, idx,   o);
        if (ov > maxfm || (ov == maxfm && oi < idx)) { maxfm = ov; idx = oi; }
    }
    if (lane == 0) {
        g_feato[b * CC2 + c]       = maxfv;
        g_feato[b * CC2 + 512 + c] = fv[idx];
    }
}

// ---------------------------------------------------------------------------
// Kernel 3: conv1d as split-K tf32 GEMM with cp.async double-buffered W.
// ---------------------------------------------------------------------------
__device__ __forceinline__ float to_tf32(float x) {
    uint32_t u;
    asm("cvt.rna.tf32.f32 %0, %1;" : "=r"(u) : "f"(x));
    return __uint_as_float(u);
}

__device__ __forceinline__ void cp16(void* smem_dst, const void* gptr) {
    uint32_t s = (uint32_t)__cvta_generic_to_shared(smem_dst);
    asm volatile("cp.async.cg.shared.global [%0], [%1], 16;" :: "r"(s), "l"(gptr));
}

extern "C" __global__ void __launch_bounds__(256, 1)
gemm_kernel(const float* __restrict__ w) {
    extern __shared__ float sh[];
    float* xs = sh;            // [4][8][128]
    float* ws = sh + 4096;     // [2][64][WS_LD]

    const int tid = threadIdx.x;
    const int split = blockIdx.x;
    const int ic0 = split * 8;

    // Prefetch W chunk j=0 (async).
    {
        float* dst = ws;
#pragma unroll
        for (int i = 0; i < 4; i++) {
            int ii = tid + i * 256;
            int oc = ii >> 4, k4 = ii & 15;
            cp16(dst + oc * WS_LD + k4 * 4,
                 w + (size_t)oc * 65536 + (size_t)ic0 * 64 + k4 * 4);
        }
        asm volatile("cp.async.commit_group;");
    }

    // Stage x rows for 4 batches, 8 ic (tf32-converted once).
    for (int i = tid; i < 4096; i += 256) {
        int m = i & 127, j = (i >> 7) & 7, b = i >> 10;
        float v = (m < MM) ? g_x[(b * CC2 + ic0 + j) * MM + m] : 0.0f;
        xs[i] = to_tf32(v);
    }

    const int wid = tid >> 5, lane = tid & 31;
    const int b = wid >> 1, mhalf = wid & 1;
    const int g = lane >> 2, t = lane & 3;
    const float* xb = xs + b * 8 * 128;

    float acc[2][8][4];
#pragma unroll
    for (int a = 0; a < 2; a++)
#pragma unroll
        for (int n = 0; n < 8; n++)
#pragma unroll
            for (int q = 0; q < 4; q++) acc[a][n][q] = 0.0f;

    for (int j = 0; j < 8; j++) {
        asm volatile("cp.async.wait_group 0;");
        __syncthreads();
        if (j < 7) {
            float* dst = ws + ((j + 1) & 1) * 64 * WS_LD;
#pragma unroll
            for (int i = 0; i < 4; i++) {
                int ii = tid + i * 256;
                int oc = ii >> 4, k4 = ii & 15;
                cp16(dst + oc * WS_LD + k4 * 4,
                     w + (size_t)oc * 65536 + (size_t)(ic0 + j + 1) * 64 + k4 * 4);
            }
            asm volatile("cp.async.commit_group;");
        }
        const float* wb = ws + (j & 1) * 64 * WS_LD;
        const float* xr = xb + j * 128;
#pragma unroll
        for (int k0 = 0; k0 < 64; k0 += 8) {
            uint32_t a0[2], a1[2], a2[2], a3[2];
#pragma unroll
            for (int mt = 0; mt < 2; mt++) {
                int lb = mhalf * 32 + mt * 16 + g;
                a0[mt] = __float_as_uint(xr[lb     + k0 + t]);
                a1[mt] = __float_as_uint(xr[lb + 8 + k0 + t]);
                a2[mt] = __float_as_uint(xr[lb     + k0 + t + 4]);
                a3[mt] = __float_as_uint(xr[lb + 8 + k0 + t + 4]);
            }
#pragma unroll
            for (int nt = 0; nt < 8; nt++) {
                uint32_t b0 = __float_as_uint(wb[(nt * 8 + g) * WS_LD + k0 + t]);
                uint32_t b1 = __float_as_uint(wb[(nt * 8 + g) * WS_LD + k0 + t + 4]);
#pragma unroll
                for (int mt = 0; mt < 2; mt++) {
                    asm volatile(
                        "mma.sync.aligned.m16n8k8.row.col.f32.tf32.tf32.f32 "
                        "{%0,%1,%2,%3}, {%4,%5,%6,%7}, {%8,%9}, {%0,%1,%2,%3};"
                        : "+f"(acc[mt][nt][0]), "+f"(acc[mt][nt][1]),
                          "+f"(acc[mt][nt][2]), "+f"(acc[mt][nt][3])
                        : "r"(a0[mt]), "r"(a1[mt]), "r"(a2[mt]), "r"(a3[mt]),
                          "r"(b0), "r"(b1));
                }
            }
        }
        __syncthreads();
    }

    float* po = &g_part[split][0];
#pragma unroll
    for (int mt = 0; mt < 2; mt++) {
        int row0 = mhalf * 32 + mt * 16 + g;
#pragma unroll
        for (int nt = 0; nt < 8; nt++) {
            int col = nt * 8 + 2 * t;
            float2 v01 = make_float2(acc[mt][nt][0], acc[mt][nt][1]);
            float2 v23 = make_float2(acc[mt][nt][2], acc[mt][nt][3]);
            *reinterpret_cast<float2*>(po + (size_t)(b * 64 + row0)     * 64 + col) = v01;
            *reinterpret_cast<float2*>(po + (size_t)(b * 64 + row0 + 8) * 64 + col) = v23;
        }
    }
}

// ---------------------------------------------------------------------------
// Kernel 4: split-K reduce. 4 threads per output element, 32 splits each.
// ---------------------------------------------------------------------------
__global__ void reduce_kernel(const float* __restrict__ bias) {
    int gid = blockIdx.x * 256 + threadIdx.x;  // 65536 threads
    int idx = gid >> 2, q = gid & 3;
    float s = 0.0f;
#pragma unroll
    for (int i = 0; i < 32; i++) s += g_part[q * 32 + i][idx];
    s += __shfl_xor_sync(0xffffffffu, s, 1);
    s += __shfl_xor_sync(0xffffffffu, s, 2);
    if (q == 0) {
        int oc = idx & 63, l = (idx >> 6) & 63, b = idx >> 12;
        if (l < LOUT) {
            float z = s + bias[oc];
            g_sw[(b * NOC + oc) * LOUT + l] = 1.0f / (1.0f + __expf(-z));
        }
    }
}

// ---------------------------------------------------------------------------
// Kernel 5: convf -> r (sigmoid attention map), per batch.
// ---------------------------------------------------------------------------
__global__ void rs_kernel(const float* __restrict__ wf, const float* __restrict__ bf) {
    __shared__ float sw[NOC * LOUT];
    __shared__ float wfs[13 * 64 * 5];
    int b = blockIdx.x, tid = threadIdx.x;
    for (int i = tid; i < NOC * LOUT; i += 256) sw[i] = g_sw[b * NOC * LOUT + i];
    for (int i = tid; i < 13 * 64 * 5; i += 256) wfs[i] = wf[i];
    __syncthreads();
    if (tid < 169) {
        int j = tid / 13, i = tid % 13;
        float a = bf[j];
        for (int ci = 0; ci < 64; ci++) {
#pragma unroll
            for (int tt = 0; tt < 5; tt++) {
                int p = 4 * i - 2 + tt;
                if (p >= 0 && p < LOUT) a += wfs[(j * 64 + ci) * 5 + tt] * sw[ci * LOUT + p];
            }
        }
        g_rs[b * 169 + tid] = 1.0f / (1.0f + __expf(-a));
    }
}

// ---------------------------------------------------------------------------
// Kernel 6: attended mean over features_f. 32 blocks (b x channel-group).
// ---------------------------------------------------------------------------
__global__ void featmean_kernel(const float* __restrict__ featf) {
    __shared__ float rs[169];
    int b = blockIdx.x >> 3, tid = threadIdx.x;
    int c0 = (blockIdx.x & 7) * 64;
    if (tid < 169) rs[tid] = g_rs[b * 169 + tid];
    __syncthreads();
    int wid = tid >> 5, lane = tid & 31;
#pragma unroll
    for (int cc = 0; cc < 8; cc++) {
        int c = c0 + cc * 8 + wid;
        const float* fp = featf + (size_t)(b * 512 + c) * 169;
        float s = 0.0f;
        for (int p = lane; p < 169; p += 32) s += fp[p] * (1.0f + rs[p]);
#pragma unroll
        for (int o = 16; o; o >>= 1) s += __shfl_xor_sync(0xffffffffu, s, o);
        if (lane == 0) g_feat[b * 512 + c] = s * (1.0f / 169.0f);
    }
}

// ---------------------------------------------------------------------------
// Kernel 7: classification head. 12 warps, one per (b, out).
// ---------------------------------------------------------------------------
__global__ void head_kernel(const float* __restrict__ hw, const float* __restrict__ hb,
                            float* __restrict__ out) {
    int wid = threadIdx.x >> 5, lane = threadIdx.x & 31;
    int b = wid / 3, o = wid % 3;
    float s = 0.0f;
    for (int c = lane; c < 1536; c += 32) {
        float f = (c < 512) ? g_feat[b * 512 + c] : g_feato[b * CC2 + (c - 512)];
        s += f * hw[o * 1536 + c];
    }
#pragma unroll
    for (int off = 16; off; off >>= 1) s += __shfl_xor_sync(0xffffffffu, s, off);
    if (lane == 0) out[b * 3 + o] = s + hb[o];
}

// ---------------------------------------------------------------------------
extern "C" void kernel_launch(void* const* d_in, const int* in_sizes, int n_in,
                              void* d_out, int out_size) {
    const float* featf = (const float*)d_in[0];
    const float* oct   = (const float*)d_in[1];
    const float* w1    = (const float*)d_in[2];
    const float* b1    = (const float*)d_in[3];
    const float* wf    = (const float*)d_in[4];
    const float* bf    = (const float*)d_in[5];
    const float* hw    = (const float*)d_in[6];
    const float* hb    = (const float*)d_in[7];
    float* out = (float*)d_out;

    pool_kernel<<<28672, 256>>>(oct);
    argsel_kernel<<<256, 256>>>();

    const int smem_bytes = (4096 + 2 * 64 * WS_LD) * sizeof(float);
    cudaFuncSetAttribute(gemm_kernel, cudaFuncAttributeMaxDynamicSharedMemorySize,
                         smem_bytes);
    gemm_kernel<<<NSPLIT, 256, smem_bytes>>>(w1);

    reduce_kernel<<<256, 256>>>(b1);
    rs_kernel<<<4, 256>>>(wf, bf);
    featmean_kernel<<<32, 256>>>(featf);
    head_kernel<<<1, 384>>>(hw, hb, out);
}

// round 3
// speedup vs baseline: 2.5087x; 1.1579x over previous
#include <cuda_runtime.h>
#include <cstdint>

#define BB 4
#define MM 112
#define CCH 512
#define CC2 1024
#define LOUT 49
#define NOC 64
#define NSPLIT 256
#define ICPC 4      // input channels per GEMM CTA
#define WS_LD 68    // padded smem row (conflict-free B frags)

__device__ float g_x[BB * CC2 * MM];
__device__ float g_feato[BB * CC2];
__device__ float g_part[NSPLIT][BB * 64 * NOC];  // 16 MB
__device__ float g_sw[BB * NOC * LOUT];
__device__ float g_rs[BB * 169];
__device__ float g_feat[BB * 512];

// ---------------------------------------------------------------------------
// Kernel 1: fused pool (avg+max over 16x16) + argmax feature selection.
// One block per (b, c); warp per slice m; then block-level argmax.
// ---------------------------------------------------------------------------
__global__ void __launch_bounds__(256) pool_kernel(const float* __restrict__ oct) {
    __shared__ float sfv[MM];
    __shared__ float sfm[MM];
    int b = blockIdx.x >> 9, c = blockIdx.x & 511;
    int tid = threadIdx.x, wid = tid >> 5, lane = tid & 31;

    for (int m = wid; m < MM; m += 8) {
        const float4* p = reinterpret_cast<const float4*>(oct)
                        + ((size_t)(b * MM + m) * CCH + c) * 64;
        float4 v0 = p[lane];
        float4 v1 = p[lane + 32];
        float s  = (v0.x + v0.y) + (v0.z + v0.w) + (v1.x + v1.y) + (v1.z + v1.w);
        float mx = fmaxf(fmaxf(fmaxf(v0.x, v0.y), fmaxf(v0.z, v0.w)),
                         fmaxf(fmaxf(v1.x, v1.y), fmaxf(v1.z, v1.w)));
#pragma unroll
        for (int o = 16; o; o >>= 1) {
            s  += __shfl_xor_sync(0xffffffffu, s, o);
            mx  = fmaxf(mx, __shfl_xor_sync(0xffffffffu, mx, o));
        }
        if (lane == 0) { sfv[m] = s * (1.0f / 256.0f); sfm[m] = mx; }
    }
    __syncthreads();

    // Write g_x rows ([b][c][m] and [b][512+c][m]).
    if (tid < MM) {
        g_x[(b * CC2 + c) * MM + tid]       = sfv[tid];
        g_x[(b * CC2 + 512 + c) * MM + tid] = sfm[tid];
    }

    // Warp 7 (no extra sync needed past __syncthreads above): argmax reductions.
    if (wid == 7) {
        float maxfv = -1e30f, maxfm = -1e30f;
        int idx = 0x7fffffff;
        for (int m = lane; m < MM; m += 32) {
            maxfv = fmaxf(maxfv, sfv[m]);
            float q = sfm[m];
            if (q > maxfm) { maxfm = q; idx = m; }
        }
#pragma unroll
        for (int o = 16; o; o >>= 1) {
            maxfv = fmaxf(maxfv, __shfl_xor_sync(0xffffffffu, maxfv, o));
            float ov = __shfl_xor_sync(0xffffffffu, maxfm, o);
            int   oi = __shfl_xor_sync(0xffffffffu, idx,   o);
            if (ov > maxfm || (ov == maxfm && oi < idx)) { maxfm = ov; idx = oi; }
        }
        if (lane == 0) {
            g_feato[b * CC2 + c]       = maxfv;   // max_m fv == mean of argmax-fv slice
            g_feato[b * CC2 + 512 + c] = sfv[idx]; // fv at argmax of fv_max
        }
    }
}

// ---------------------------------------------------------------------------
// Kernel 2: conv1d as split-K tf32 GEMM, 256 CTAs (4 ic each), 2 CTAs/SM.
// ---------------------------------------------------------------------------
__device__ __forceinline__ float to_tf32(float x) {
    uint32_t u;
    asm("cvt.rna.tf32.f32 %0, %1;" : "=r"(u) : "f"(x));
    return __uint_as_float(u);
}

__device__ __forceinline__ void cp16(void* smem_dst, const void* gptr) {
    uint32_t s = (uint32_t)__cvta_generic_to_shared(smem_dst);
    asm volatile("cp.async.cg.shared.global [%0], [%1], 16;" :: "r"(s), "l"(gptr));
}

extern "C" __global__ void __launch_bounds__(256, 2)
gemm_kernel(const float* __restrict__ w) {
    extern __shared__ float sh[];
    float* xs = sh;            // [4][ICPC][128] = 2048 floats
    float* ws = sh + 2048;     // [2][64][WS_LD]

    const int tid = threadIdx.x;
    const int split = blockIdx.x;
    const int ic0 = split * ICPC;

    // Prefetch W chunk j=0 (async).
#pragma unroll
    for (int i = 0; i < 4; i++) {
        int ii = tid + i * 256;
        int oc = ii >> 4, k4 = ii & 15;
        cp16(ws + oc * WS_LD + k4 * 4,
             w + (size_t)oc * 65536 + (size_t)ic0 * 64 + k4 * 4);
    }
    asm volatile("cp.async.commit_group;");

    // Stage x rows (tf32-converted once).
    for (int i = tid; i < 4 * ICPC * 128; i += 256) {
        int m = i & 127, j = (i >> 7) & (ICPC - 1), b = i >> 9;
        float v = (m < MM) ? g_x[(b * CC2 + ic0 + j) * MM + m] : 0.0f;
        xs[i] = to_tf32(v);
    }

    const int wid = tid >> 5, lane = tid & 31;
    const int b = wid >> 1, mhalf = wid & 1;
    const int g = lane >> 2, t = lane & 3;
    const float* xb = xs + b * ICPC * 128;

    float acc[2][8][4];
#pragma unroll
    for (int a = 0; a < 2; a++)
#pragma unroll
        for (int n = 0; n < 8; n++)
#pragma unroll
            for (int q = 0; q < 4; q++) acc[a][n][q] = 0.0f;

    for (int j = 0; j < ICPC; j++) {
        asm volatile("cp.async.wait_group 0;");
        __syncthreads();
        if (j < ICPC - 1) {
            float* dst = ws + ((j + 1) & 1) * 64 * WS_LD;
#pragma unroll
            for (int i = 0; i < 4; i++) {
                int ii = tid + i * 256;
                int oc = ii >> 4, k4 = ii & 15;
                cp16(dst + oc * WS_LD + k4 * 4,
                     w + (size_t)oc * 65536 + (size_t)(ic0 + j + 1) * 64 + k4 * 4);
            }
            asm volatile("cp.async.commit_group;");
        }
        const float* wb = ws + (j & 1) * 64 * WS_LD;
        const float* xr = xb + j * 128;
#pragma unroll
        for (int k0 = 0; k0 < 64; k0 += 8) {
            uint32_t a0[2], a1[2], a2[2], a3[2];
#pragma unroll
            for (int mt = 0; mt < 2; mt++) {
                int lb = mhalf * 32 + mt * 16 + g;
                a0[mt] = __float_as_uint(xr[lb     + k0 + t]);
                a1[mt] = __float_as_uint(xr[lb + 8 + k0 + t]);
                a2[mt] = __float_as_uint(xr[lb     + k0 + t + 4]);
                a3[mt] = __float_as_uint(xr[lb + 8 + k0 + t + 4]);
            }
#pragma unroll
            for (int nt = 0; nt < 8; nt++) {
                uint32_t b0 = __float_as_uint(wb[(nt * 8 + g) * WS_LD + k0 + t]);
                uint32_t b1 = __float_as_uint(wb[(nt * 8 + g) * WS_LD + k0 + t + 4]);
#pragma unroll
                for (int mt = 0; mt < 2; mt++) {
                    asm volatile(
                        "mma.sync.aligned.m16n8k8.row.col.f32.tf32.tf32.f32 "
                        "{%0,%1,%2,%3}, {%4,%5,%6,%7}, {%8,%9}, {%0,%1,%2,%3};"
                        : "+f"(acc[mt][nt][0]), "+f"(acc[mt][nt][1]),
                          "+f"(acc[mt][nt][2]), "+f"(acc[mt][nt][3])
                        : "r"(a0[mt]), "r"(a1[mt]), "r"(a2[mt]), "r"(a3[mt]),
                          "r"(b0), "r"(b1));
                }
            }
        }
        __syncthreads();
    }

    float* po = &g_part[split][0];
#pragma unroll
    for (int mt = 0; mt < 2; mt++) {
        int row0 = mhalf * 32 + mt * 16 + g;
#pragma unroll
        for (int nt = 0; nt < 8; nt++) {
            int col = nt * 8 + 2 * t;
            float2 v01 = make_float2(acc[mt][nt][0], acc[mt][nt][1]);
            float2 v23 = make_float2(acc[mt][nt][2], acc[mt][nt][3]);
            *reinterpret_cast<float2*>(po + (size_t)(b * 64 + row0)     * 64 + col) = v01;
            *reinterpret_cast<float2*>(po + (size_t)(b * 64 + row0 + 8) * 64 + col) = v23;
        }
    }
}

// ---------------------------------------------------------------------------
// Kernel 3: split-K reduce, coalesced. Block: 8 q-groups x 32 idx.
// ---------------------------------------------------------------------------
__global__ void __launch_bounds__(256) reduce_kernel(const float* __restrict__ bias) {
    __shared__ float acc[8][32];
    int tid = threadIdx.x;
    int q = tid >> 5, r = tid & 31;
    int idx = blockIdx.x * 32 + r;
    float s = 0.0f;
#pragma unroll
    for (int i = 0; i < 32; i++) s += g_part[q * 32 + i][idx];
    acc[q][r] = s;
    __syncthreads();
    if (q == 0) {
        float t = acc[0][r] + acc[1][r] + acc[2][r] + acc[3][r]
                + acc[4][r] + acc[5][r] + acc[6][r] + acc[7][r];
        int oc = idx & 63, l = (idx >> 6) & 63, b = idx >> 12;
        if (l < LOUT) {
            float z = t + bias[oc];
            g_sw[(b * NOC + oc) * LOUT + l] = 1.0f / (1.0f + __expf(-z));
        }
    }
}

// ---------------------------------------------------------------------------
// Kernel 4: convf -> r (sigmoid attention map), per batch.
// ---------------------------------------------------------------------------
__global__ void rs_kernel(const float* __restrict__ wf, const float* __restrict__ bf) {
    __shared__ float sw[NOC * LOUT];
    __shared__ float wfs[13 * 64 * 5];
    int b = blockIdx.x, tid = threadIdx.x;
    for (int i = tid; i < NOC * LOUT; i += 256) sw[i] = g_sw[b * NOC * LOUT + i];
    for (int i = tid; i < 13 * 64 * 5; i += 256) wfs[i] = wf[i];
    __syncthreads();
    if (tid < 169) {
        int j = tid / 13, i = tid % 13;
        float a = bf[j];
        for (int ci = 0; ci < 64; ci++) {
#pragma unroll
            for (int tt = 0; tt < 5; tt++) {
                int p = 4 * i - 2 + tt;
                if (p >= 0 && p < LOUT) a += wfs[(j * 64 + ci) * 5 + tt] * sw[ci * LOUT + p];
            }
        }
        g_rs[b * 169 + tid] = 1.0f / (1.0f + __expf(-a));
    }
}

// ---------------------------------------------------------------------------
// Kernel 5: attended mean over features_f. 64 blocks.
// ---------------------------------------------------------------------------
__global__ void __launch_bounds__(256) featmean_kernel(const float* __restrict__ featf) {
    __shared__ float rs[169];
    int b = blockIdx.x >> 4, tid = threadIdx.x;
    int c0 = (blockIdx.x & 15) * 32;
    if (tid < 169) rs[tid] = g_rs[b * 169 + tid];
    __syncthreads();
    int wid = tid >> 5, lane = tid & 31;
#pragma unroll
    for (int cc = 0; cc < 4; cc++) {
        int c = c0 + cc * 8 + wid;
        const float* fp = featf + (size_t)(b * 512 + c) * 169;
        float s = 0.0f;
        for (int p = lane; p < 169; p += 32) s += fp[p] * (1.0f + rs[p]);
#pragma unroll
        for (int o = 16; o; o >>= 1) s += __shfl_xor_sync(0xffffffffu, s, o);
        if (lane == 0) g_feat[b * 512 + c] = s * (1.0f / 169.0f);
    }
}

// ---------------------------------------------------------------------------
// Kernel 6: classification head. 12 warps, one per (b, out).
// ---------------------------------------------------------------------------
__global__ void head_kernel(const float* __restrict__ hw, const float* __restrict__ hb,
                            float* __restrict__ out) {
    int wid = threadIdx.x >> 5, lane = threadIdx.x & 31;
    int b = wid / 3, o = wid % 3;
    float s = 0.0f;
    for (int c = lane; c < 1536; c += 32) {
        float f = (c < 512) ? g_feat[b * 512 + c] : g_feato[b * CC2 + (c - 512)];
        s += f * hw[o * 1536 + c];
    }
#pragma unroll
    for (int off = 16; off; off >>= 1) s += __shfl_xor_sync(0xffffffffu, s, off);
    if (lane == 0) out[b * 3 + o] = s + hb[o];
}

// ---------------------------------------------------------------------------
extern "C" void kernel_launch(void* const* d_in, const int* in_sizes, int n_in,
                              void* d_out, int out_size) {
    const float* featf = (const float*)d_in[0];
    const float* oct   = (const float*)d_in[1];
    const float* w1    = (const float*)d_in[2];
    const float* b1    = (const float*)d_in[3];
    const float* wf    = (const float*)d_in[4];
    const float* bf    = (const float*)d_in[5];
    const float* hw    = (const float*)d_in[6];
    const float* hb    = (const float*)d_in[7];
    float* out = (float*)d_out;

    pool_kernel<<<2048, 256>>>(oct);

    const int smem_bytes = (2048 + 2 * 64 * WS_LD) * sizeof(float);  // ~43 KB
    cudaFuncSetAttribute(gemm_kernel, cudaFuncAttributeMaxDynamicSharedMemorySize,
                         smem_bytes);
    gemm_kernel<<<NSPLIT, 256, smem_bytes>>>(w1);

    reduce_kernel<<<512, 256>>>(b1);
    rs_kernel<<<4, 256>>>(wf, bf);
    featmean_kernel<<<64, 256>>>(featf);
    head_kernel<<<1, 384>>>(hw, hb, out);
}